// round 8
// baseline (speedup 1.0000x reference)
#include <cuda_runtime.h>

#define N_ 256
#define M_ 512
#define D_ 64
#define ROWS_ 8
#define CTAS_ (M_ / ROWS_)   // 64
#define CHUNKS_ 8            // N_/32
#define EPSF 1e-6f
#define INFF 1e30f
#define CANARY_U 0xF149F2CAu   // == -1e30f: impossible output value, NOT NaN

// ---------------- device scratch (no allocations allowed) ----------------
__device__ float g_dists[M_ * N_];        // d[m][n]
__device__ float g_w[N_ * N_];            // w[n][t]
__device__ float g_wN[N_];                // p_back[N][t]
__device__ float g_CbarX[CTAS_][N_ * N_]; // per-CTA boundary Cbar (canary init)
__device__ float g_Cb[CTAS_][N_];         // per-CTA boundary C row (canary init)
__device__ int   g_ticket;

// ---------------- helpers ----------------
// L2-coherent read: bypasses (incoherent) L1 but does NOT discard the L2 line
// (ld.cv would force a DRAM refetch and miss L2-resident producer stores).
__device__ __forceinline__ float ld_vol(const float* p) {
    float v;
    asm volatile("ld.volatile.global.f32 %0, [%1];" : "=f"(v) : "l"(p));
    return v;
}
__device__ __forceinline__ float wait_valid(const float* p, float v) {
    while (__float_as_uint(v) == CANARY_U) v = ld_vol(p);
    return v;
}
__device__ __forceinline__ int lds_acquire(const int* p) {
    int v;
    unsigned a = (unsigned)__cvta_generic_to_shared((const void*)p);
    asm volatile("ld.acquire.cta.shared.b32 %0, [%1];" : "=r"(v) : "r"(a) : "memory");
    return v;
}
__device__ __forceinline__ void sts_release(int* p, int v) {
    unsigned a = (unsigned)__cvta_generic_to_shared((void*)p);
    asm volatile("st.release.cta.shared.b32 [%0], %1;" :: "r"(a), "r"(v) : "memory");
}
__device__ __forceinline__ float warp_sum(float v) {
#pragma unroll
    for (int o = 16; o; o >>= 1) v += __shfl_xor_sync(0xffffffffu, v, o);
    return v;
}

// ---------------- kernel: reset mutable state each launch ----------------
__global__ void pal_reset_kernel() {
    const float cf = __uint_as_float(CANARY_U);
    const float4 c4 = make_float4(cf, cf, cf, cf);
    int idx = blockIdx.x * blockDim.x + threadIdx.x;
    int stride = gridDim.x * blockDim.x;
    float4* pb = reinterpret_cast<float4*>(&g_CbarX[0][0]);
    const int total = CTAS_ * N_ * N_ / 4;
    for (int i = idx; i < total; i += stride) pb[i] = c4;
    float4* pc = reinterpret_cast<float4*>(&g_Cb[0][0]);
    if (idx < CTAS_ * N_ / 4) pc[idx] = c4;
    if (idx == 0) g_ticket = 0;
}

// ---------------- kernel: pairwise L2 distances ----------------
__global__ void pal_dists_kernel(const float* __restrict__ x,
                                 const float* __restrict__ y) {
    __shared__ float sx[D_];
    int m = blockIdx.x;
    int t = threadIdx.x;
    if (t < D_) sx[t] = x[m * D_ + t];
    __syncthreads();
    const float4* y4 = reinterpret_cast<const float4*>(y + (size_t)t * D_);
    float acc = 0.f;
#pragma unroll
    for (int i = 0; i < D_ / 4; i++) {
        float4 v = y4[i];
        float d0 = sx[4 * i + 0] - v.x;
        float d1 = sx[4 * i + 1] - v.y;
        float d2 = sx[4 * i + 2] - v.z;
        float d3 = sx[4 * i + 3] - v.w;
        acc += d0 * d0 + d1 * d1 + d2 * d2 + d3 * d3;
    }
    g_dists[m * N_ + t] = sqrtf(acc);
}

// ---------------- kernel: reachability p, mixing weights w ----------------
__global__ void pal_reach_kernel(const float* __restrict__ q) {
    __shared__ float sp[N_ + 1];
    int tid = threadIdx.x;
    bool act = (tid <= N_);
    float preg = (tid == 0) ? 1.f : 0.f;
    if (tid == 0) sp[0] = 1.f;
    const float4* qrow = act ? reinterpret_cast<const float4*>(q + (size_t)tid * N_)
                             : reinterpret_cast<const float4*>(q);
    float4 qcur = qrow[0];
    float4 qnxt = qrow[1];
    __syncthreads();
    for (int nb = 0; nb < N_; nb++) {
        float pnb = sp[nb];
        int s = nb & 3;
        float qv = (s == 0) ? qcur.x : (s == 1) ? qcur.y : (s == 2) ? qcur.z : qcur.w;
        preg = fmaf(pnb, qv, preg);
        if (s == 3) {
            qcur = qnxt;
            int g = (nb >> 2) + 2;
            qnxt = qrow[g < N_ / 4 ? g : N_ / 4 - 1];
        }
        if (tid == nb + 1) sp[nb + 1] = preg;
        __syncthreads();
    }
    if (act) sp[tid] = preg;
    __syncthreads();
    float pN = sp[N_];
    for (int idx = tid; idx < N_ * N_; idx += blockDim.x) {
        int n = idx >> 8;
        int t = idx & (N_ - 1);
        g_w[idx] = sp[t] * q[idx] / (sp[n] + EPSF);
    }
    if (tid < N_) g_wN[tid] = sp[tid] * q[N_ * N_ + tid] / (pN + EPSF);
}

// ---------------- kernel: decoupled wavefront DP ----------------
// CTA bid owns rows [bid*8, bid*8+8), one warp per row, no CTA barrier.
// Intra-CTA: smem flags (cta-scope release/acquire) + depth-4 cbar ring.
// Cross-CTA: per-boundary buffers g_CbarX[bid]/g_Cb[bid], canary-initialized;
// producer (warp 7) plain-stores (write-through to L2), consumer (warp 0)
// volatile L2 reads + per-element canary retry — self-validating data, no
// flags, one L2 round trip, fully prefetch-overlapped.
__global__ void __launch_bounds__(256, 1) pal_dp_kernel(float* __restrict__ out) {
    __shared__ float sd[ROWS_][N_];             // distance rows
    __shared__ float sC[ROWS_][N_];             // published C rows (warps 0..6)
    __shared__ float sbuf[ROWS_ - 1][4][N_];    // cbar rings between adjacent rows
    __shared__ int   sflag[ROWS_];              // data flags (columns published)
    __shared__ int   rflag[ROWS_];              // consumer progress flags
    __shared__ int   sm_bid;

    const int tid = threadIdx.x;
    const int w   = tid >> 5;
    const int l   = tid & 31;

    if (tid == 0) sm_bid = atomicAdd(&g_ticket, 1);
    if (tid < ROWS_) { sflag[tid] = 0; rflag[tid] = 0; }
    __syncthreads();
    const int bid = sm_bid;
    const int m   = bid * ROWS_ + w;

#pragma unroll
    for (int r = 0; r < ROWS_; r++)
        sd[r][tid] = __ldg(&g_dists[(bid * ROWS_ + r) * N_ + tid]);
    __syncthreads();

    const bool mz  = (m == 0);
    const bool gup = (w == 0 && bid > 0);
    const float* upCbar = g_CbarX[(bid > 0) ? bid - 1 : 0];
    const float* upC    = g_Cb[(bid > 0) ? bid - 1 : 0];
    float* myCbar = g_CbarX[bid];
    float* myC    = g_Cb[bid];

    float Cown[CHUNKS_], Cpr[CHUNKS_], wv[CHUNKS_], cbnP[CHUNKS_];
#pragma unroll
    for (int c = 0; c < CHUNKS_; c++) { Cown[c] = INFF; Cpr[c] = INFF; cbnP[c] = INFF; }
    float vprevP = INFF;
    int   fcache = 0, rcache = 0;
    float dcur = sd[w][0];

    // ---- column 0 ----
    {
        float base = 0.f;
        if (!mz) {
            if (w == 0) {
                base = wait_valid(&upC[0], ld_vol(&upC[0]));
            } else {
                while (fcache < 1) fcache = lds_acquire(&sflag[w - 1]);
                base = sC[w - 1][0];
            }
        }
        float c0 = dcur + base;
        if (l == 0) {
            Cown[0] = c0;
            if (!mz) Cpr[0] = base;
            if (w < ROWS_ - 1) { sC[w][0] = c0; sts_release(&sflag[w], 1); }
            else               { myC[0] = c0; }
        }
        dcur = sd[w][1];
#pragma unroll
        for (int c = 0; c < CHUNKS_; c++) wv[c] = __ldg(&g_w[1 * N_ + c * 32 + l]);
        if (gup) {
            vprevP = base;   // C[m-1][0], validated
#pragma unroll
            for (int c = 0; c < CHUNKS_; c++)
                cbnP[c] = ld_vol(&upCbar[1 * N_ + c * 32 + l]);
        }
    }

    // ---- columns 1..N-1 (per-warp loop, no CTA barrier) ----
    for (int n = 1; n < N_; n++) {
        const int slot = n & 3;
        float cbarv[CHUNKS_];
        float vprev = INFF;

        if (!mz) {
            if (w == 0) {
                // validate prefetched cross-CTA data (canary retry, t<n only)
#pragma unroll
                for (int c = 0; c < CHUNKS_; c++) {
                    const int t = c * 32 + l;
                    float v = cbnP[c];
                    if (t < n) v = wait_valid(&upCbar[n * N_ + t], v);
                    cbarv[c] = v;
                }
                vprev = wait_valid(&upC[n - 1], vprevP);
            } else {
                if (fcache < n + 1) {
                    do { fcache = lds_acquire(&sflag[w - 1]); } while (fcache < n + 1);
                }
#pragma unroll
                for (int c = 0; c < CHUNKS_; c++)
                    cbarv[c] = sbuf[w - 1][slot][c * 32 + l];
                vprev = sC[w - 1][n - 1];
            }
        } else {
#pragma unroll
            for (int c = 0; c < CHUNKS_; c++) cbarv[c] = INFF;
        }

        // registerize C[m-1][n-1]
        {
            const int cc = (n - 1) >> 5, ll = (n - 1) & 31;
#pragma unroll
            for (int c = 0; c < CHUNKS_; c++)
                if (c == cc && l == ll) Cpr[c] = vprev;
        }

        const float dmn = dcur;
        float acc0 = 0.f, acc1 = 0.f;
        float cbst[CHUNKS_];
#pragma unroll
        for (int c = 0; c < CHUNKS_; c++) {
            const int t = c * 32 + l;
            float mn = fminf(Cown[c], fminf(Cpr[c], cbarv[c]));
            float cb = dmn + mn;
            cbst[c] = cb;
            float pr = (t < n) ? wv[c] * cb : 0.f;
            if (c & 1) acc1 += pr; else acc0 += pr;
        }
        float accp = acc0 + acc1;

        // publish cbar row BEFORE the reduce
        if (w < ROWS_ - 1) {
            if (n >= 4 && rcache < n - 3) {
                do { rcache = lds_acquire(&rflag[w + 1]); } while (rcache < n - 3);
            }
#pragma unroll
            for (int c = 0; c < CHUNKS_; c++) {
                int t = c * 32 + l;
                if (t < n) sbuf[w][slot][t] = cbst[c];
            }
            __syncwarp();
            if (l == 0) sts_release(&sflag[w], n + 1);
            if (l == 1 && w >= 1) sts_release(&rflag[w], n + 1);
        } else {
            // canary-protocol publish: per-element, self-validating
#pragma unroll
            for (int c = 0; c < CHUNKS_; c++) {
                int t = c * 32 + l;
                if (t < n) myCbar[n * N_ + t] = cbst[c];
            }
            if (l == 1) sts_release(&rflag[ROWS_ - 1], n + 1);
        }

        // warp reduce (own-column chain only)
        float acc = warp_sum(accp);

        {
            const int cc = n >> 5, ll = n & 31;
#pragma unroll
            for (int c = 0; c < CHUNKS_; c++)
                if (c == cc && l == ll) Cown[c] = acc;
        }
        if (w < ROWS_ - 1) { if (l == 0) sC[w][n] = acc; }
        else               { if (l == 0) myC[n] = acc; }

        // prefetch next column inputs
        const int nn = (n + 1 < N_) ? n + 1 : N_ - 1;
        dcur = sd[w][nn];
#pragma unroll
        for (int c = 0; c < CHUNKS_; c++) wv[c] = __ldg(&g_w[nn * N_ + c * 32 + l]);
        if (gup && n + 1 < N_) {
#pragma unroll
            for (int c = 0; c < CHUNKS_; c++)
                cbnP[c] = ld_vol(&upCbar[(n + 1) * N_ + c * 32 + l]);
            vprevP = ld_vol(&upC[n]);
        }
    }

    // ---- final: out = sum_t p_back[N][t] * C[M-1][t] ----
    if (bid == CTAS_ - 1 && w == ROWS_ - 1) {
        float v = 0.f;
#pragma unroll
        for (int c = 0; c < CHUNKS_; c++)
            v += __ldg(&g_wN[c * 32 + l]) * Cown[c];
        v = warp_sum(v);
        if (l == 0) out[0] = v;
    }
}

// ---------------- launch ----------------
extern "C" void kernel_launch(void* const* d_in, const int* in_sizes, int n_in,
                              void* d_out, int out_size) {
    const float* x = (const float*)d_in[0];   // (512, 64)
    const float* y = (const float*)d_in[1];   // (256, 64)
    const float* q = (const float*)d_in[2];   // (257, 256)
    float* out = (float*)d_out;

    pal_reset_kernel<<<2048, 256>>>();
    pal_dists_kernel<<<M_, N_>>>(x, y);
    pal_reach_kernel<<<1, 512>>>(q);
    pal_dp_kernel<<<CTAS_, 256>>>(out);
}